// round 2
// baseline (speedup 1.0000x reference)
#include <cuda_runtime.h>

// HSEGNNFlexLayer: fused message passing layer.
//   m  = swish(tp(cat(x[dst],x[src],amf), eattr, W1,b1))
//   m  = swish(tp(m, eattr, W2,b2))
//   agg= segment_sum(m, dst)
//   u  = swish(tp(cat(x,agg,anf), nattr, W3,b3))
//   out= tp(u, nattr, W4,b4)
// tp(a,b,W)[e,o] = sum_{i,k} a[e,i] b[e,k] W[i,k,o]
//
// Strategy: per thread keep t[e=8][k=8] accumulators (packed as f32x2),
// t[e,k] = sum_i a[e,i] W[i,k,o]; epilogue folds b (8 values) + bias + act.
// W streamed L2->smem in 16-row chunks; inputs gathered to an i-major smem
// tile so the inner loop is 2x LDS.128 (broadcast) + 8 LDS + 32 fma.f32x2.

#define DN 128
#define AN 8
#define EB 32
#define IC 16
#define NT 512
#define NNODE 50000
#define NEDGE 500000

__device__ float g_agg[(size_t)NNODE * DN];

typedef unsigned long long u64;

__device__ __forceinline__ u64 pk2(float lo, float hi) {
  u64 r;
  asm("mov.b64 %0, {%1,%2};" : "=l"(r) : "f"(lo), "f"(hi));
  return r;
}
__device__ __forceinline__ void fma2(u64& d, u64 a, u64 b) {
  asm("fma.rn.f32x2 %0, %1, %2, %0;" : "+l"(d) : "l"(a), "l"(b));
}
__device__ __forceinline__ void up2(u64 v, float& lo, float& hi) {
  asm("mov.b64 {%0,%1}, %2;" : "=f"(lo), "=f"(hi) : "l"(v));
}
__device__ __forceinline__ float swishf(float z) {
  return z * (1.f / (1.f + __expf(-z)));
}

// Accumulate t2[e][k-pair] = sum_i a[e,i] * W[i,k,o] over i in [0,IN).
// Thread layout: o = tid&127, eg = tid>>7 -> edges eg*8..eg*8+7 of the tile.
template <typename Loader>
__device__ __forceinline__ void tp_acc(u64 (&t2)[8][4],
                                       const float* __restrict__ Wg, int IN,
                                       float* Ws, float* As, int tid, int o,
                                       int eg, Loader load_a) {
#pragma unroll
  for (int e = 0; e < 8; e++)
#pragma unroll
    for (int k = 0; k < 4; k++) t2[e][k] = 0ull;

  const int nchunk = (IN + IC - 1) / IC;
  const int wtot = IN * AN * DN;
  for (int c = 0; c < nchunk; c++) {
    const int base = c * (IC * AN * DN);
    // stage W chunk [IC][8][128] (contiguous in global) into smem
#pragma unroll
    for (int j = 0; j < (IC * AN * DN) / (4 * NT); j++) {  // 8 float4/thread
      int idx4 = j * NT + tid;
      int g = base + idx4 * 4;
      float4 v = make_float4(0.f, 0.f, 0.f, 0.f);
      if (g < wtot) v = *(const float4*)(Wg + g);
      *(float4*)(Ws + idx4 * 4) = v;
    }
    // stage a chunk, i-major: As[il][e]
    {
      int il = tid >> 5, e = tid & 31;
      As[il * EB + e] = load_a(c * IC + il, e);
    }
    __syncthreads();
#pragma unroll 4
    for (int il = 0; il < IC; il++) {
      const float* wrow = Ws + il * (AN * DN) + o;
      u64 wp[4];
#pragma unroll
      for (int k = 0; k < 4; k++)
        wp[k] = pk2(wrow[(2 * k) * DN], wrow[(2 * k + 1) * DN]);
      const float4 a0 = *(const float4*)(As + il * EB + eg * 8);
      const float4 a1 = *(const float4*)(As + il * EB + eg * 8 + 4);
      float av[8] = {a0.x, a0.y, a0.z, a0.w, a1.x, a1.y, a1.z, a1.w};
#pragma unroll
      for (int e = 0; e < 8; e++) {
        u64 ap = pk2(av[e], av[e]);
#pragma unroll
        for (int k = 0; k < 4; k++) fma2(t2[e][k], ap, wp[k]);
      }
    }
    __syncthreads();
  }
}

extern __shared__ float smem[];

// smem layout (floats): Ws[16384] | As[512] | buf[32*129] | batt[256] | idx
#define SM_AS (IC * AN * DN)
#define SM_BUF (SM_AS + IC * EB)
#define SM_BATT (SM_BUF + EB * (DN + 1))
#define SM_IDX (SM_BATT + EB * AN)
#define SMEM_BYTES ((SM_IDX + 2 * EB) * 4)

__global__ void __launch_bounds__(NT, 1)
    msg_kernel(const float* __restrict__ x, const int* __restrict__ eidx,
               const float* __restrict__ eattr, const float* __restrict__ amf,
               const float* __restrict__ W1, const float* __restrict__ b1,
               const float* __restrict__ W2, const float* __restrict__ b2) {
  float* Ws = smem;
  float* As = smem + SM_AS;
  float* m1 = smem + SM_BUF;
  float* batt = smem + SM_BATT;
  int* dsts = (int*)(smem + SM_IDX);
  int* srcs = dsts + EB;

  const int tid = threadIdx.x;
  const int o = tid & (DN - 1);
  const int eg = tid >> 7;
  const int e0 = blockIdx.x * EB;

  if (tid < EB) {
    srcs[tid] = eidx[e0 + tid];          // row 0 = src (j)
    dsts[tid] = eidx[NEDGE + e0 + tid];  // row 1 = dst (i)
  }
  if (tid < EB * AN) batt[tid] = eattr[(size_t)e0 * AN + tid];
  __syncthreads();

  u64 t2[8][4];

  // ---- layer 1: in = cat(x[dst], x[src], amf), IN=259 ----
  tp_acc(t2, W1, 2 * DN + 3, Ws, As, tid, o, eg, [&](int i, int e) -> float {
    if (i < DN) return x[(size_t)dsts[e] * DN + i];
    if (i < 2 * DN) return x[(size_t)srcs[e] * DN + (i - DN)];
    if (i < 2 * DN + 3) return amf[(size_t)(e0 + e) * 3 + (i - 2 * DN)];
    return 0.f;
  });

  {
    const float bias = b1[o];
#pragma unroll
    for (int e = 0; e < 8; e++) {
      int ee = eg * 8 + e;
      float z = bias;
#pragma unroll
      for (int k = 0; k < 4; k++) {
        float lo, hi;
        up2(t2[e][k], lo, hi);
        z += batt[ee * AN + 2 * k] * lo + batt[ee * AN + 2 * k + 1] * hi;
      }
      m1[ee * (DN + 1) + o] = swishf(z);
    }
  }
  __syncthreads();

  // ---- layer 2: in = m1, IN=128 ----
  tp_acc(t2, W2, DN, Ws, As, tid, o, eg,
         [&](int i, int e) -> float { return m1[e * (DN + 1) + i]; });

  {
    const float bias = b2[o];
#pragma unroll
    for (int e = 0; e < 8; e++) {
      int ee = eg * 8 + e;
      float z = bias;
#pragma unroll
      for (int k = 0; k < 4; k++) {
        float lo, hi;
        up2(t2[e][k], lo, hi);
        z += batt[ee * AN + 2 * k] * lo + batt[ee * AN + 2 * k + 1] * hi;
      }
      atomicAdd(&g_agg[(size_t)dsts[ee] * DN + o], swishf(z));
    }
  }
}

__global__ void __launch_bounds__(NT, 1)
    upd_kernel(const float* __restrict__ x, const float* __restrict__ nattr,
               const float* __restrict__ anf, const float* __restrict__ W3,
               const float* __restrict__ b3, const float* __restrict__ W4,
               const float* __restrict__ b4, float* __restrict__ out) {
  float* Ws = smem;
  float* As = smem + SM_AS;
  float* ub = smem + SM_BUF;
  float* batt = smem + SM_BATT;

  const int tid = threadIdx.x;
  const int o = tid & (DN - 1);
  const int eg = tid >> 7;
  const int n0 = blockIdx.x * EB;

  if (tid < EB * AN) {
    int nn = n0 + tid / AN;
    batt[tid] = (nn < NNODE) ? nattr[(size_t)nn * AN + (tid % AN)] : 0.f;
  }
  __syncthreads();

  u64 t2[8][4];

  // ---- layer 3: in = cat(x, agg, anf), IN=259 ----
  tp_acc(t2, W3, 2 * DN + 3, Ws, As, tid, o, eg, [&](int i, int e) -> float {
    int nn = n0 + e;
    if (nn >= NNODE) return 0.f;
    if (i < DN) return x[(size_t)nn * DN + i];
    if (i < 2 * DN) return g_agg[(size_t)nn * DN + (i - DN)];
    if (i < 2 * DN + 3) return anf[(size_t)nn * 3 + (i - 2 * DN)];
    return 0.f;
  });

  {
    const float bias = b3[o];
#pragma unroll
    for (int e = 0; e < 8; e++) {
      int ee = eg * 8 + e;
      float z = bias;
#pragma unroll
      for (int k = 0; k < 4; k++) {
        float lo, hi;
        up2(t2[e][k], lo, hi);
        z += batt[ee * AN + 2 * k] * lo + batt[ee * AN + 2 * k + 1] * hi;
      }
      ub[ee * (DN + 1) + o] = swishf(z);
    }
  }
  __syncthreads();

  // ---- layer 4: in = u, IN=128, no activation ----
  tp_acc(t2, W4, DN, Ws, As, tid, o, eg,
         [&](int i, int e) -> float { return ub[e * (DN + 1) + i]; });

  {
    const float bias = b4[o];
#pragma unroll
    for (int e = 0; e < 8; e++) {
      int ee = eg * 8 + e;
      int nn = n0 + ee;
      float z = bias;
#pragma unroll
      for (int k = 0; k < 4; k++) {
        float lo, hi;
        up2(t2[e][k], lo, hi);
        z += batt[ee * AN + 2 * k] * lo + batt[ee * AN + 2 * k + 1] * hi;
      }
      if (nn < NNODE) out[(size_t)nn * DN + o] = z;
    }
  }
}

__global__ void zero_agg_kernel() {
  int i = blockIdx.x * blockDim.x + threadIdx.x;
  ((float4*)g_agg)[i] = make_float4(0.f, 0.f, 0.f, 0.f);
}

extern "C" void kernel_launch(void* const* d_in, const int* in_sizes, int n_in,
                              void* d_out, int out_size) {
  const float *x = 0, *eattr = 0, *nattr = 0, *amf = 0, *anf = 0;
  const float *W1 = 0, *W2 = 0, *W3 = 0, *W4 = 0;
  const float *b1 = 0, *b2 = 0, *b3 = 0, *b4 = 0;
  const int* eidx = 0;
  int c265 = 0, c131 = 0, cb = 0;
  for (int i = 0; i < n_in; i++) {
    const void* p = d_in[i];
    switch (in_sizes[i]) {
      case 6400000: x = (const float*)p; break;          // [N,128]
      case 1000000: eidx = (const int*)p; break;         // [2,E] int32
      case 4000000: eattr = (const float*)p; break;      // [E,8]
      case 400000:  nattr = (const float*)p; break;      // [N,8]
      case 1500000: amf = (const float*)p; break;        // [E,3]
      case 150000:  anf = (const float*)p; break;        // [N,3]
      case 265216:  if (c265++ == 0) W1 = (const float*)p; else W3 = (const float*)p; break;
      case 131072:  if (c131++ == 0) W2 = (const float*)p; else W4 = (const float*)p; break;
      case 128:
        if (cb == 0) b1 = (const float*)p;
        else if (cb == 1) b2 = (const float*)p;
        else if (cb == 2) b3 = (const float*)p;
        else b4 = (const float*)p;
        cb++;
        break;
      default: break;  // batch (50000) unused
    }
  }

  cudaFuncSetAttribute(msg_kernel, cudaFuncAttributeMaxDynamicSharedMemorySize,
                       SMEM_BYTES);
  cudaFuncSetAttribute(upd_kernel, cudaFuncAttributeMaxDynamicSharedMemorySize,
                       SMEM_BYTES);

  zero_agg_kernel<<<(NNODE * DN / 4) / 256, 256>>>();
  msg_kernel<<<NEDGE / EB, NT, SMEM_BYTES>>>(x, eidx, eattr, amf, W1, b1, W2,
                                             b2);
  upd_kernel<<<(NNODE + EB - 1) / EB, NT, SMEM_BYTES>>>(x, nattr, anf, W3, b3,
                                                        W4, b4, (float*)d_out);
}

// round 12
// speedup vs baseline: 1.9400x; 1.9400x over previous
#include <cuda_runtime.h>
#include <cstdint>

#define DN 128
#define AN 8
#define EB 32
#define IC 16
#define NT 512
#define NNODE 50000
#define NEDGE 500000

__device__ float g_agg[(size_t)NNODE * DN];
__device__ float g_P[(size_t)NNODE * 1024];
__device__ float g_Q[(size_t)NNODE * 1024];

typedef unsigned long long u64;

__device__ __forceinline__ u64 pk2(float lo, float hi) {
  u64 r;
  asm("mov.b64 %0, {%1,%2};" : "=l"(r) : "f"(lo), "f"(hi));
  return r;
}
__device__ __forceinline__ void fma2(u64& d, u64 a, u64 b) {
  asm("fma.rn.f32x2 %0, %1, %2, %0;" : "+l"(d) : "l"(a), "l"(b));
}
__device__ __forceinline__ void up2(u64 v, float& lo, float& hi) {
  asm("mov.b64 {%0,%1}, %2;" : "=f"(lo), "=f"(hi) : "l"(v));
}
__device__ __forceinline__ float swishf(float z) {
  return z * (1.f / (1.f + __expf(-z)));
}

// t2[e][k2] = sum_i a[e,i] * W[i,k,o]  (R1-proven structure, unchanged)
template <typename Loader>
__device__ __forceinline__ void tp_acc(u64 (&t2)[8][4],
                                       const float* __restrict__ Wg, int IN,
                                       float* Ws, float* As, int tid, int o,
                                       int eg, Loader load_a) {
#pragma unroll
  for (int e = 0; e < 8; e++)
#pragma unroll
    for (int k = 0; k < 4; k++) t2[e][k] = 0ull;
  const int nchunk = (IN + IC - 1) / IC;
  const int wtot = IN * AN * DN;
  for (int c = 0; c < nchunk; c++) {
    const int base = c * (IC * AN * DN);
#pragma unroll
    for (int j = 0; j < (IC * AN * DN) / (4 * NT); j++) {
      int idx4 = j * NT + tid;
      int g = base + idx4 * 4;
      float4 v = make_float4(0.f, 0.f, 0.f, 0.f);
      if (g < wtot) v = *(const float4*)(Wg + g);
      *(float4*)(Ws + idx4 * 4) = v;
    }
    {
      int il = tid >> 5, e2 = tid & 31;
      As[il * EB + e2] = load_a(c * IC + il, e2);
    }
    __syncthreads();
#pragma unroll 4
    for (int il = 0; il < IC; il++) {
      const float* wrow = Ws + il * (AN * DN) + o;
      u64 wp[4];
#pragma unroll
      for (int k = 0; k < 4; k++)
        wp[k] = pk2(wrow[(2 * k) * DN], wrow[(2 * k + 1) * DN]);
      const float4 a0 = *(const float4*)(As + il * EB + eg * 8);
      const float4 a1 = *(const float4*)(As + il * EB + eg * 8 + 4);
      float av[8] = {a0.x, a0.y, a0.z, a0.w, a1.x, a1.y, a1.z, a1.w};
#pragma unroll
      for (int e = 0; e < 8; e++) {
        u64 ap = pk2(av[e], av[e]);
#pragma unroll
        for (int k = 0; k < 4; k++) fma2(t2[e][k], ap, wp[k]);
      }
    }
    __syncthreads();
  }
}

extern __shared__ float smem[];

// smem float offsets (shared by all kernels)
#define SM_AS 16384
#define SM_BUF (SM_AS + IC * EB)                 // 16896: m1/ub [32][129]
#define SM_BATT (SM_BUF + EB * (DN + 1))        // 21024: battrs [32][8]
#define SM_AMF (SM_BATT + EB * AN)              // 21280: amf [32][3]
#define SM_IDX (SM_AMF + EB * 3)                // 21376: dst/src [2][32]
#define SMEMB ((SM_IDX + 2 * EB) * 4)

// P[n,k,o] = sum_i x[n,i] W1[i,k,o];  Q[n,k,o] = sum_i x[n,i] W1[128+i,k,o]
__global__ void __launch_bounds__(NT, 1)
    build_pq_kernel(const float* __restrict__ x, const float* __restrict__ W1) {
  float* Ws = smem;
  float* As = smem + SM_AS;
  const int tid = threadIdx.x;
  const int o = tid & (DN - 1);
  const int eg = tid >> 7;
  const int n0 = blockIdx.x * EB;
  u64 t2[8][4];
  auto ldx = [&](int i, int e) -> float {
    int nn = n0 + e;
    return (nn < NNODE && i < DN) ? x[(size_t)nn * DN + i] : 0.f;
  };
  tp_acc(t2, W1, DN, Ws, As, tid, o, eg, ldx);
#pragma unroll
  for (int e = 0; e < 8; e++) {
    int nn = n0 + eg * 8 + e;
    if (nn < NNODE) {
#pragma unroll
      for (int k = 0; k < 4; k++) {
        float lo, hi;
        up2(t2[e][k], lo, hi);
        g_P[(size_t)nn * 1024 + (2 * k) * DN + o] = lo;
        g_P[(size_t)nn * 1024 + (2 * k + 1) * DN + o] = hi;
      }
    }
  }
  __syncthreads();
  tp_acc(t2, W1 + (size_t)DN * AN * DN, DN, Ws, As, tid, o, eg, ldx);
#pragma unroll
  for (int e = 0; e < 8; e++) {
    int nn = n0 + eg * 8 + e;
    if (nn < NNODE) {
#pragma unroll
      for (int k = 0; k < 4; k++) {
        float lo, hi;
        up2(t2[e][k], lo, hi);
        g_Q[(size_t)nn * 1024 + (2 * k) * DN + o] = lo;
        g_Q[(size_t)nn * 1024 + (2 * k + 1) * DN + o] = hi;
      }
    }
  }
}

// msg: phase1 m1 = swish(b-fold(P[dst]+Q[src]+amf*W1amf) + b1);
//      phase2 = R1 layer-2 bilinear + atomic scatter.
__global__ void __launch_bounds__(NT, 1)
    msg_kernel(const int* __restrict__ eidx, const float* __restrict__ eattr,
               const float* __restrict__ amf, const float* __restrict__ W1,
               const float* __restrict__ b1, const float* __restrict__ W2,
               const float* __restrict__ b2) {
  float* Ws = smem;
  float* As = smem + SM_AS;
  float* m1 = smem + SM_BUF;
  float* batt = smem + SM_BATT;
  float* amfs = smem + SM_AMF;
  int* dsts = (int*)(smem + SM_IDX);
  int* srcs = dsts + EB;
  const int tid = threadIdx.x;
  const int o = tid & (DN - 1);
  const int eg = tid >> 7;
  const int e0 = blockIdx.x * EB;  // NEDGE = 32 * 15625 exactly
  if (tid < EB) {
    srcs[tid] = eidx[e0 + tid];
    dsts[tid] = eidx[NEDGE + e0 + tid];
  }
  if (tid < EB * AN) batt[tid] = eattr[(size_t)e0 * AN + tid];
  if (tid < EB * 3) amfs[tid] = amf[(size_t)e0 * 3 + tid];
  // stage W1 rows 256..258 ([3][8][128] = 3072 floats = 768 float4) into Ws
  {
    const float4* src4 = (const float4*)(W1 + (size_t)256 * AN * DN);
    for (int j = tid; j < 768; j += NT) ((float4*)Ws)[j] = src4[j];
  }
  __syncthreads();

  // ---- phase 1: fold P[dst] + Q[src] + amf-term with edge attrs ----
  {
    const float bias = b1[o];
#pragma unroll 2
    for (int e = 0; e < 8; e++) {
      int ee = eg * 8 + e;
      const float* Pp = g_P + (size_t)dsts[ee] * 1024 + o;
      const float* Qp = g_Q + (size_t)srcs[ee] * 1024 + o;
      float a0 = amfs[ee * 3], a1 = amfs[ee * 3 + 1], a2 = amfs[ee * 3 + 2];
      float z = bias;
#pragma unroll
      for (int k = 0; k < AN; k++) {
        float wk = a0 * Ws[k * DN + o] + a1 * Ws[1024 + k * DN + o] +
                   a2 * Ws[2048 + k * DN + o];
        z += batt[ee * AN + k] * (Pp[k * DN] + Qp[k * DN] + wk);
      }
      m1[ee * (DN + 1) + o] = swishf(z);
    }
  }
  __syncthreads();

  // ---- phase 2: layer 2 bilinear ----
  u64 t2[8][4];
  tp_acc(t2, W2, DN, Ws, As, tid, o, eg,
         [&](int i, int e) -> float { return m1[e * (DN + 1) + i]; });
  {
    const float bias = b2[o];
#pragma unroll
    for (int e = 0; e < 8; e++) {
      int ee = eg * 8 + e;
      float z = bias;
#pragma unroll
      for (int k = 0; k < 4; k++) {
        float lo, hi;
        up2(t2[e][k], lo, hi);
        z += batt[ee * AN + 2 * k] * lo + batt[ee * AN + 2 * k + 1] * hi;
      }
      atomicAdd(&g_agg[(size_t)dsts[ee] * DN + o], swishf(z));
    }
  }
}

__global__ void __launch_bounds__(NT, 1)
    upd_kernel(const float* __restrict__ x, const float* __restrict__ nattr,
               const float* __restrict__ anf, const float* __restrict__ W3,
               const float* __restrict__ b3, const float* __restrict__ W4,
               const float* __restrict__ b4, float* __restrict__ out) {
  float* Ws = smem;
  float* As = smem + SM_AS;
  float* ub = smem + SM_BUF;
  float* batt = smem + SM_BATT;
  const int tid = threadIdx.x;
  const int o = tid & (DN - 1);
  const int eg = tid >> 7;
  const int n0 = blockIdx.x * EB;
  if (tid < EB * AN) {
    int nn = n0 + tid / AN;
    batt[tid] = (nn < NNODE) ? nattr[(size_t)nn * AN + (tid % AN)] : 0.f;
  }
  __syncthreads();
  u64 t2[8][4];
  tp_acc(t2, W3, 2 * DN + 3, Ws, As, tid, o, eg, [&](int i, int e) -> float {
    int nn = n0 + e;
    if (nn >= NNODE) return 0.f;
    if (i < DN) return x[(size_t)nn * DN + i];
    if (i < 2 * DN) return g_agg[(size_t)nn * DN + (i - DN)];
    if (i < 2 * DN + 3) return anf[(size_t)nn * 3 + (i - 2 * DN)];
    return 0.f;
  });
  {
    const float bias = b3[o];
#pragma unroll
    for (int e = 0; e < 8; e++) {
      int ee = eg * 8 + e;
      float z = bias;
#pragma unroll
      for (int k = 0; k < 4; k++) {
        float lo, hi;
        up2(t2[e][k], lo, hi);
        z += batt[ee * AN + 2 * k] * lo + batt[ee * AN + 2 * k + 1] * hi;
      }
      ub[ee * (DN + 1) + o] = swishf(z);
    }
  }
  __syncthreads();
  tp_acc(t2, W4, DN, Ws, As, tid, o, eg,
         [&](int i, int e) -> float { return ub[e * (DN + 1) + i]; });
  {
    const float bias = b4[o];
#pragma unroll
    for (int e = 0; e < 8; e++) {
      int ee = eg * 8 + e;
      int nn = n0 + ee;
      float z = bias;
#pragma unroll
      for (int k = 0; k < 4; k++) {
        float lo, hi;
        up2(t2[e][k], lo, hi);
        z += batt[ee * AN + 2 * k] * lo + batt[ee * AN + 2 * k + 1] * hi;
      }
      if (nn < NNODE) out[(size_t)nn * DN + o] = z;
    }
  }
}

__global__ void zero_agg_kernel() {
  int i = blockIdx.x * blockDim.x + threadIdx.x;
  ((float4*)g_agg)[i] = make_float4(0.f, 0.f, 0.f, 0.f);
}

extern "C" void kernel_launch(void* const* d_in, const int* in_sizes, int n_in,
                              void* d_out, int out_size) {
  const float *x = 0, *eattr = 0, *nattr = 0, *amf = 0, *anf = 0;
  const float *W1 = 0, *W2 = 0, *W3 = 0, *W4 = 0;
  const float *b1 = 0, *b2 = 0, *b3 = 0, *b4 = 0;
  const int* eidx = 0;
  int c265 = 0, c131 = 0, cb = 0;
  for (int i = 0; i < n_in; i++) {
    const void* p = d_in[i];
    switch (in_sizes[i]) {
      case 6400000: x = (const float*)p; break;          // [N,128]
      case 1000000: eidx = (const int*)p; break;         // [2,E]
      case 4000000: eattr = (const float*)p; break;      // [E,8]
      case 400000:  nattr = (const float*)p; break;      // [N,8]
      case 1500000: amf = (const float*)p; break;        // [E,3]
      case 150000:  anf = (const float*)p; break;        // [N,3]
      case 265216:  if (c265++ == 0) W1 = (const float*)p; else W3 = (const float*)p; break;
      case 131072:  if (c131++ == 0) W2 = (const float*)p; else W4 = (const float*)p; break;
      case 128:
        if (cb == 0) b1 = (const float*)p;
        else if (cb == 1) b2 = (const float*)p;
        else if (cb == 2) b3 = (const float*)p;
        else b4 = (const float*)p;
        cb++;
        break;
      default: break;  // batch unused
    }
  }

  cudaFuncSetAttribute(build_pq_kernel,
                       cudaFuncAttributeMaxDynamicSharedMemorySize, SMEMB);
  cudaFuncSetAttribute(msg_kernel, cudaFuncAttributeMaxDynamicSharedMemorySize,
                       SMEMB);
  cudaFuncSetAttribute(upd_kernel, cudaFuncAttributeMaxDynamicSharedMemorySize,
                       SMEMB);

  zero_agg_kernel<<<(NNODE * DN / 4) / 256, 256>>>();
  build_pq_kernel<<<(NNODE + EB - 1) / EB, NT, SMEMB>>>(x, W1);
  msg_kernel<<<NEDGE / EB, NT, SMEMB>>>(eidx, eattr, amf, W1, b1, W2, b2);
  upd_kernel<<<(NNODE + EB - 1) / EB, NT, SMEMB>>>(x, nattr, anf, W3, b3, W4,
                                                   b4, (float*)d_out);
}

// round 13
// speedup vs baseline: 2.2295x; 1.1493x over previous
#include <cuda_runtime.h>
#include <cstdint>

#define DN 128
#define AN 8
#define EB 32
#define IC 16
#define NT 512
#define NNODE 50000
#define NEDGE 500000
#define CHF (IC * AN * DN)  // 16384 floats per W chunk

__device__ float g_agg[(size_t)NNODE * DN];
__device__ float g_P[(size_t)NNODE * 1024];
__device__ float g_Q[(size_t)NNODE * 1024];

typedef unsigned long long u64;

__device__ __forceinline__ u64 pk2(float lo, float hi) {
  u64 r;
  asm("mov.b64 %0, {%1,%2};" : "=l"(r) : "f"(lo), "f"(hi));
  return r;
}
__device__ __forceinline__ void fma2(u64& d, u64 a, u64 b) {
  asm("fma.rn.f32x2 %0, %1, %2, %0;" : "+l"(d) : "l"(a), "l"(b));
}
__device__ __forceinline__ void up2(u64 v, float& lo, float& hi) {
  asm("mov.b64 {%0,%1}, %2;" : "=f"(lo), "=f"(hi) : "l"(v));
}
__device__ __forceinline__ float swishf(float z) {
  return z * (1.f / (1.f + __expf(-z)));
}
__device__ __forceinline__ uint32_t sm2u(const void* p) {
  uint32_t a;
  asm("{ .reg .u64 t; cvta.to.shared.u64 t, %1; cvt.u32.u64 %0, t; }"
      : "=r"(a) : "l"(p));
  return a;
}
__device__ __forceinline__ void cpa16(uint32_t dst, const float* src, int ok) {
  asm volatile("cp.async.cg.shared.global [%0],[%1],16,%2;" ::"r"(dst),
               "l"(src), "r"(ok) : "memory");
}
__device__ __forceinline__ void cpa4(uint32_t dst, const float* src, int ok) {
  asm volatile("cp.async.ca.shared.global [%0],[%1],4,%2;" ::"r"(dst),
               "l"(src), "r"(ok) : "memory");
}
__device__ __forceinline__ void cpcommit() {
  asm volatile("cp.async.commit_group;" ::: "memory");
}
__device__ __forceinline__ void cpwait1() {
  asm volatile("cp.async.wait_group 1;" ::: "memory");
}
__device__ __forceinline__ void cpwait0() {
  asm volatile("cp.async.wait_group 0;" ::: "memory");
}

// shared compute for one staged chunk (identical math to R12)
__device__ __forceinline__ void tp_compute(u64 (&t2)[8][4], const float* Wsb,
                                           const float* Asb, int o, int eg) {
#pragma unroll 4
  for (int il = 0; il < IC; il++) {
    const float* wrow = Wsb + il * (AN * DN) + o;
    u64 wp[4];
#pragma unroll
    for (int k = 0; k < 4; k++)
      wp[k] = pk2(wrow[(2 * k) * DN], wrow[(2 * k + 1) * DN]);
    const float4 a0 = *(const float4*)(Asb + il * EB + eg * 8);
    const float4 a1 = *(const float4*)(Asb + il * EB + eg * 8 + 4);
    float av[8] = {a0.x, a0.y, a0.z, a0.w, a1.x, a1.y, a1.z, a1.w};
#pragma unroll
    for (int e = 0; e < 8; e++) {
      u64 ap = pk2(av[e], av[e]);
#pragma unroll
      for (int k = 0; k < 4; k++) fma2(t2[e][k], ap, wp[k]);
    }
  }
}

// double-buffered, cp.async-staged; Loader returns global ptr (or null = 0)
template <typename PL>
__device__ __forceinline__ void tp_accG(u64 (&t2)[8][4],
                                        const float* __restrict__ Wg, int IN,
                                        float* Ws, float* As, int tid, int o,
                                        int eg, PL L) {
#pragma unroll
  for (int e = 0; e < 8; e++)
#pragma unroll
    for (int k = 0; k < 4; k++) t2[e][k] = 0ull;
  const int nchunk = (IN + IC - 1) / IC;
  const int wtot = IN * AN * DN;
  const int il_t = tid >> 5, e_t = tid & 31;
  const uint32_t ws_u = sm2u(Ws), as_u = sm2u(As);

  {  // stage chunk 0 -> buf 0
#pragma unroll
    for (int j = 0; j < CHF / (4 * NT); j++) {
      int idx4 = j * NT + tid;
      int g = idx4 * 4;
      int ok = (g < wtot) ? 16 : 0;
      cpa16(ws_u + idx4 * 16, Wg + (ok ? g : 0), ok);
    }
    const float* p = L(il_t, e_t);
    cpa4(as_u + (il_t * EB + e_t) * 4, p ? p : Wg, p ? 4 : 0);
    cpcommit();
  }
  for (int c = 0; c < nchunk; c++) {
    const int b = c & 1;
    if (c + 1 < nchunk) {
      const int nb = b ^ 1;
#pragma unroll
      for (int j = 0; j < CHF / (4 * NT); j++) {
        int idx4 = j * NT + tid;
        int g = (c + 1) * CHF + idx4 * 4;
        int ok = (g < wtot) ? 16 : 0;
        cpa16(ws_u + (nb * CHF + idx4 * 4) * 4, Wg + (ok ? g : 0), ok);
      }
      const float* p = L((c + 1) * IC + il_t, e_t);
      cpa4(as_u + (nb * 512 + il_t * EB + e_t) * 4, p ? p : Wg, p ? 4 : 0);
      cpcommit();
      cpwait1();
    } else {
      cpwait0();
    }
    __syncthreads();
    tp_compute(t2, Ws + b * CHF, As + b * 512, o, eg);
    __syncthreads();
  }
}

// double-buffered W via cp.async; a comes from smem (value loader)
template <typename VL>
__device__ __forceinline__ void tp_accS(u64 (&t2)[8][4],
                                        const float* __restrict__ Wg, int IN,
                                        float* Ws, float* As, int tid, int o,
                                        int eg, VL L) {
#pragma unroll
  for (int e = 0; e < 8; e++)
#pragma unroll
    for (int k = 0; k < 4; k++) t2[e][k] = 0ull;
  const int nchunk = (IN + IC - 1) / IC;
  const int wtot = IN * AN * DN;
  const int il_t = tid >> 5, e_t = tid & 31;
  const uint32_t ws_u = sm2u(Ws);

  {
#pragma unroll
    for (int j = 0; j < CHF / (4 * NT); j++) {
      int idx4 = j * NT + tid;
      int g = idx4 * 4;
      int ok = (g < wtot) ? 16 : 0;
      cpa16(ws_u + idx4 * 16, Wg + (ok ? g : 0), ok);
    }
    cpcommit();
    As[il_t * EB + e_t] = L(il_t, e_t);
  }
  for (int c = 0; c < nchunk; c++) {
    const int b = c & 1;
    if (c + 1 < nchunk) {
      const int nb = b ^ 1;
#pragma unroll
      for (int j = 0; j < CHF / (4 * NT); j++) {
        int idx4 = j * NT + tid;
        int g = (c + 1) * CHF + idx4 * 4;
        int ok = (g < wtot) ? 16 : 0;
        cpa16(ws_u + (nb * CHF + idx4 * 4) * 4, Wg + (ok ? g : 0), ok);
      }
      cpcommit();
      As[nb * 512 + il_t * EB + e_t] = L((c + 1) * IC + il_t, e_t);
      cpwait1();
    } else {
      cpwait0();
    }
    __syncthreads();
    tp_compute(t2, Ws + b * CHF, As + b * 512, o, eg);
    __syncthreads();
  }
}

extern __shared__ float smem[];

// smem float offsets
#define SM_WS 0                           // 2 x 16384
#define SM_AS (2 * CHF)                   // 32768: 2 x 512
#define SM_BUF (SM_AS + 2 * IC * EB)      // 33792: m1/ub [32][129]
#define SM_BATT (SM_BUF + EB * (DN + 1))  // 37920
#define SM_AMF (SM_BATT + EB * AN)        // 38176
#define SM_IDX (SM_AMF + EB * 3)          // 38272
#define SMEMB ((SM_IDX + 2 * EB) * 4)     // 153344 B

// P[n,k,o] = sum_i x[n,i] W1[i,k,o];  Q: rows 128..255 of W1
__global__ void __launch_bounds__(NT, 1)
    build_pq_kernel(const float* __restrict__ x, const float* __restrict__ W1) {
  float* Ws = smem + SM_WS;
  float* As = smem + SM_AS;
  const int tid = threadIdx.x;
  const int o = tid & (DN - 1);
  const int eg = tid >> 7;
  const int n0 = blockIdx.x * EB;
  u64 t2[8][4];
  auto ldx = [&](int i, int e) -> const float* {
    int nn = n0 + e;
    return (nn < NNODE) ? x + (size_t)nn * DN + i : (const float*)0;
  };
  tp_accG(t2, W1, DN, Ws, As, tid, o, eg, ldx);
#pragma unroll
  for (int e = 0; e < 8; e++) {
    int nn = n0 + eg * 8 + e;
    if (nn < NNODE) {
#pragma unroll
      for (int k = 0; k < 4; k++) {
        float lo, hi;
        up2(t2[e][k], lo, hi);
        g_P[(size_t)nn * 1024 + (2 * k) * DN + o] = lo;
        g_P[(size_t)nn * 1024 + (2 * k + 1) * DN + o] = hi;
      }
    }
  }
  __syncthreads();
  tp_accG(t2, W1 + (size_t)DN * AN * DN, DN, Ws, As, tid, o, eg, ldx);
#pragma unroll
  for (int e = 0; e < 8; e++) {
    int nn = n0 + eg * 8 + e;
    if (nn < NNODE) {
#pragma unroll
      for (int k = 0; k < 4; k++) {
        float lo, hi;
        up2(t2[e][k], lo, hi);
        g_Q[(size_t)nn * 1024 + (2 * k) * DN + o] = lo;
        g_Q[(size_t)nn * 1024 + (2 * k + 1) * DN + o] = hi;
      }
    }
  }
}

// msg: phase1 m1 = swish(b-fold(P[dst]+Q[src]+amf-term) + b1); phase2 = L2.
__global__ void __launch_bounds__(NT, 1)
    msg_kernel(const int* __restrict__ eidx, const float* __restrict__ eattr,
               const float* __restrict__ amf, const float* __restrict__ W1,
               const float* __restrict__ b1, const float* __restrict__ W2,
               const float* __restrict__ b2) {
  float* Ws = smem + SM_WS;
  float* As = smem + SM_AS;
  float* m1 = smem + SM_BUF;
  float* batt = smem + SM_BATT;
  float* amfs = smem + SM_AMF;
  int* dsts = (int*)(smem + SM_IDX);
  int* srcs = dsts + EB;
  const int tid = threadIdx.x;
  const int o = tid & (DN - 1);
  const int eg = tid >> 7;
  const int e0 = blockIdx.x * EB;  // NEDGE divisible by EB
  if (tid < EB) {
    srcs[tid] = eidx[e0 + tid];
    dsts[tid] = eidx[NEDGE + e0 + tid];
  }
  if (tid < EB * AN) batt[tid] = eattr[(size_t)e0 * AN + tid];
  if (tid < EB * 3) amfs[tid] = amf[(size_t)e0 * 3 + tid];
  // stage W1 amf rows 256..258 (3072 floats = 768 float4) into Ws
  {
    const float4* src4 = (const float4*)(W1 + (size_t)256 * AN * DN);
    for (int j = tid; j < 768; j += NT) ((float4*)Ws)[j] = src4[j];
  }
  __syncthreads();

  // ---- phase 1 ----
  {
    const float bias = b1[o];
#pragma unroll 2
    for (int e = 0; e < 8; e++) {
      int ee = eg * 8 + e;
      const float* Pp = g_P + (size_t)dsts[ee] * 1024 + o;
      const float* Qp = g_Q + (size_t)srcs[ee] * 1024 + o;
      float a0 = amfs[ee * 3], a1 = amfs[ee * 3 + 1], a2 = amfs[ee * 3 + 2];
      float z = bias;
#pragma unroll
      for (int k = 0; k < AN; k++) {
        float wk = a0 * Ws[k * DN + o] + a1 * Ws[1024 + k * DN + o] +
                   a2 * Ws[2048 + k * DN + o];
        z += batt[ee * AN + k] * (Pp[k * DN] + Qp[k * DN] + wk);
      }
      m1[ee * (DN + 1) + o] = swishf(z);
    }
  }
  __syncthreads();

  // ---- phase 2: layer 2 bilinear ----
  u64 t2[8][4];
  tp_accS(t2, W2, DN, Ws, As, tid, o, eg,
          [&](int i, int e) -> float { return m1[e * (DN + 1) + i]; });
  {
    const float bias = b2[o];
#pragma unroll
    for (int e = 0; e < 8; e++) {
      int ee = eg * 8 + e;
      float z = bias;
#pragma unroll
      for (int k = 0; k < 4; k++) {
        float lo, hi;
        up2(t2[e][k], lo, hi);
        z += batt[ee * AN + 2 * k] * lo + batt[ee * AN + 2 * k + 1] * hi;
      }
      atomicAdd(&g_agg[(size_t)dsts[ee] * DN + o], swishf(z));
    }
  }
}

__global__ void __launch_bounds__(NT, 1)
    upd_kernel(const float* __restrict__ x, const float* __restrict__ nattr,
               const float* __restrict__ anf, const float* __restrict__ W3,
               const float* __restrict__ b3, const float* __restrict__ W4,
               const float* __restrict__ b4, float* __restrict__ out) {
  float* Ws = smem + SM_WS;
  float* As = smem + SM_AS;
  float* ub = smem + SM_BUF;
  float* batt = smem + SM_BATT;
  const int tid = threadIdx.x;
  const int o = tid & (DN - 1);
  const int eg = tid >> 7;
  const int n0 = blockIdx.x * EB;
  if (tid < EB * AN) {
    int nn = n0 + tid / AN;
    batt[tid] = (nn < NNODE) ? nattr[(size_t)nn * AN + (tid % AN)] : 0.f;
  }
  __syncthreads();
  u64 t2[8][4];
  tp_accG(t2, W3, 2 * DN + 3, Ws, As, tid, o, eg,
          [&](int i, int e) -> const float* {
            int nn = n0 + e;
            if (nn >= NNODE) return (const float*)0;
            if (i < DN) return x + (size_t)nn * DN + i;
            if (i < 2 * DN) return g_agg + (size_t)nn * DN + (i - DN);
            if (i < 2 * DN + 3) return anf + (size_t)nn * 3 + (i - 2 * DN);
            return (const float*)0;
          });
  {
    const float bias = b3[o];
#pragma unroll
    for (int e = 0; e < 8; e++) {
      int ee = eg * 8 + e;
      float z = bias;
#pragma unroll
      for (int k = 0; k < 4; k++) {
        float lo, hi;
        up2(t2[e][k], lo, hi);
        z += batt[ee * AN + 2 * k] * lo + batt[ee * AN + 2 * k + 1] * hi;
      }
      ub[ee * (DN + 1) + o] = swishf(z);
    }
  }
  __syncthreads();
  tp_accS(t2, W4, DN, Ws, As, tid, o, eg,
          [&](int i, int e) -> float { return ub[e * (DN + 1) + i]; });
  {
    const float bias = b4[o];
#pragma unroll
    for (int e = 0; e < 8; e++) {
      int ee = eg * 8 + e;
      int nn = n0 + ee;
      float z = bias;
#pragma unroll
      for (int k = 0; k < 4; k++) {
        float lo, hi;
        up2(t2[e][k], lo, hi);
        z += batt[ee * AN + 2 * k] * lo + batt[ee * AN + 2 * k + 1] * hi;
      }
      if (nn < NNODE) out[(size_t)nn * DN + o] = z;
    }
  }
}

__global__ void zero_agg_kernel() {
  int i = blockIdx.x * blockDim.x + threadIdx.x;
  ((float4*)g_agg)[i] = make_float4(0.f, 0.f, 0.f, 0.f);
}

extern "C" void kernel_launch(void* const* d_in, const int* in_sizes, int n_in,
                              void* d_out, int out_size) {
  const float *x = 0, *eattr = 0, *nattr = 0, *amf = 0, *anf = 0;
  const float *W1 = 0, *W2 = 0, *W3 = 0, *W4 = 0;
  const float *b1 = 0, *b2 = 0, *b3 = 0, *b4 = 0;
  const int* eidx = 0;
  int c265 = 0, c131 = 0, cb = 0;
  for (int i = 0; i < n_in; i++) {
    const void* p = d_in[i];
    switch (in_sizes[i]) {
      case 6400000: x = (const float*)p; break;          // [N,128]
      case 1000000: eidx = (const int*)p; break;         // [2,E]
      case 4000000: eattr = (const float*)p; break;      // [E,8]
      case 400000:  nattr = (const float*)p; break;      // [N,8]
      case 1500000: amf = (const float*)p; break;        // [E,3]
      case 150000:  anf = (const float*)p; break;        // [N,3]
      case 265216:  if (c265++ == 0) W1 = (const float*)p; else W3 = (const float*)p; break;
      case 131072:  if (c131++ == 0) W2 = (const float*)p; else W4 = (const float*)p; break;
      case 128:
        if (cb == 0) b1 = (const float*)p;
        else if (cb == 1) b2 = (const float*)p;
        else if (cb == 2) b3 = (const float*)p;
        else b4 = (const float*)p;
        cb++;
        break;
      default: break;  // batch unused
    }
  }

  cudaFuncSetAttribute(build_pq_kernel,
                       cudaFuncAttributeMaxDynamicSharedMemorySize, SMEMB);
  cudaFuncSetAttribute(msg_kernel, cudaFuncAttributeMaxDynamicSharedMemorySize,
                       SMEMB);
  cudaFuncSetAttribute(upd_kernel, cudaFuncAttributeMaxDynamicSharedMemorySize,
                       SMEMB);

  zero_agg_kernel<<<(NNODE * DN / 4) / 256, 256>>>();
  build_pq_kernel<<<(NNODE + EB - 1) / EB, NT, SMEMB>>>(x, W1);
  msg_kernel<<<NEDGE / EB, NT, SMEMB>>>(eidx, eattr, amf, W1, b1, W2, b2);
  upd_kernel<<<(NNODE + EB - 1) / EB, NT, SMEMB>>>(x, nattr, anf, W3, b3, W4,
                                                   b4, (float*)d_out);
}